// round 1
// baseline (speedup 1.0000x reference)
#include <cuda_runtime.h>
#include <cstdint>

// MaxUnpool2D: B=8, H=W=128, C=64, KH=KW=2, HOUT=WOUT=256.
// Mask guarantees: each input element's target lies inside its own 2x2 output
// window; windows are disjoint => unique targets => plain stores, and the
// union of all windows tiles the output exactly => no zero-fill pass needed.
//
// Each thread: 4 channels (float4 x, int4 mask), writes 4 output float4s
// (one per window position), selecting value-or-zero per component.

#define B_ 8
#define H_ 128
#define W_ 128
#define C_ 64
#define HOUT_ 256
#define WOUT_ 256
#define C4_ (C_ / 4)   // 16 float4 groups per pixel

__global__ void __launch_bounds__(256)
max_unpool_kernel(const float4* __restrict__ x4,
                  const int4* __restrict__ m4,
                  float4* __restrict__ out4)
{
    const int tid = blockIdx.x * blockDim.x + threadIdx.x;
    // tid layout: (((b*H + h)*W + w) * C4 + c4)
    const int c4 = tid & (C4_ - 1);
    int rem = tid >> 4;           // log2(C4_) = 4
    const int w = rem & (W_ - 1);
    rem >>= 7;                    // log2(W_) = 7
    const int h = rem & (H_ - 1);
    const int b = rem >> 7;       // log2(H_) = 7

    // Input: float4 index == tid exactly (layout matches).
    const float4 v = x4[tid];
    const int4   m = m4[tid];

    const int c0 = c4 * 4;               // first channel of this group
    const int ho = h * 2;
    const int wo = w * 2;

    // Per-batch output base in float4 units.
    const int out_base4 = b * (HOUT_ * WOUT_ * C4_);

    const float vx[4] = {v.x, v.y, v.z, v.w};
    const int   mi[4] = {m.x, m.y, m.z, m.w};

#pragma unroll
    for (int dh = 0; dh < 2; ++dh) {
#pragma unroll
        for (int dw = 0; dw < 2; ++dw) {
            // Flat elem index (per batch) of channel 0 of this window position,
            // TF layout: (ho*WOUT + wo)*C + c.
            const int pos_flat0 = ((ho + dh) * WOUT_ + (wo + dw)) * C_ + c0;
            float4 o;
            o.x = (mi[0] == pos_flat0 + 0) ? vx[0] : 0.0f;
            o.y = (mi[1] == pos_flat0 + 1) ? vx[1] : 0.0f;
            o.z = (mi[2] == pos_flat0 + 2) ? vx[2] : 0.0f;
            o.w = (mi[3] == pos_flat0 + 3) ? vx[3] : 0.0f;
            out4[out_base4 + (pos_flat0 >> 2)] = o;
        }
    }
}

extern "C" void kernel_launch(void* const* d_in, const int* in_sizes, int n_in,
                              void* d_out, int out_size)
{
    const float4* x4 = (const float4*)d_in[0];  // input_pool f32 [8,128,128,64]
    const int4*   m4 = (const int4*)d_in[1];    // pool_mask  i32 [8,128,128,64]
    float4* out4 = (float4*)d_out;              // [8,256,256,64] f32

    const int n_threads = (B_ * H_ * W_ * C_) / 4;  // 2,097,152
    const int block = 256;
    const int grid = n_threads / block;             // 8192
    max_unpool_kernel<<<grid, block>>>(x4, m4, out4);
}